// round 1
// baseline (speedup 1.0000x reference)
#include <cuda_runtime.h>

// LocalGConv: out[b,u,o] = relu( sum_s adj[s,u,:] @ (x[b] @ W[s]) [:,o] + bias[o] )
// B=32768, V=43, DIN=DOUT=64, S=2.  Fully fused: x read once, out written once.
// Per CTA: GB batches sequentially; W/adj/bias cached in SMEM across batches.

#define BTOT  32768
#define V     43
#define DIN   64
#define DOUT  64
#define NS    2
#define GB    4
#define NT    128

#define SM_W      (NS*DIN*DOUT)      // 8192 floats
#define SM_ADJ_P  3700               // 2*43*43 = 3698, padded to mult of 4
#define SM_X      (V*DIN)            // 2752
#define SM_PRE    (NS*V*DOUT)        // 5504
#define SMEM_FLOATS (SM_W + SM_ADJ_P + SM_X + SM_PRE + DOUT)
#define SMEM_BYTES  (SMEM_FLOATS * 4)

__global__ __launch_bounds__(NT, 2)
void lgconv_kernel(const float* __restrict__ gx,
                   const float* __restrict__ gadj,
                   const float* __restrict__ gw,
                   const float* __restrict__ gb,
                   float* __restrict__ gout)
{
    extern __shared__ float sm[];
    float* sW   = sm;                    // [s][i][o]
    float* sAdj = sW + SM_W;             // [s][u][v]
    float* sX   = sAdj + SM_ADJ_P;       // [v][i]
    float* sPre = sX + SM_X;             // [s][v][o]
    float* sB   = sPre + SM_PRE;         // [o]

    const int tid = threadIdx.x;

    // ---- cooperative load of W / adj / bias (once per CTA) ----
    {
        const float4* src = (const float4*)gw;
        float4* dst = (float4*)sW;
        for (int i = tid; i < SM_W / 4; i += NT) dst[i] = src[i];
        for (int i = tid; i < NS * V * V; i += NT) sAdj[i] = gadj[i];
        if (tid < DOUT) sB[tid] = gb[tid];
    }

    const int ot = tid & 7;        // 8 o-groups, each owns 8 consecutive o
    const int vt = tid >> 3;       // 16 row-groups
    const int O  = ot * 8;
    const int v0 = vt;
    const int v1 = vt + 16;        // always < 43
    const int v2 = vt + 32;
    const bool has3 = (v2 < V);
    const int v2c = has3 ? v2 : v0;  // clamp: compute garbage, never store

    for (int g = 0; g < GB; ++g) {
        const int b = blockIdx.x * GB + g;

        // ---- load x_b into SMEM ----
        {
            const float4* src = (const float4*)(gx + (size_t)b * SM_X);
            float4* dst = (float4*)sX;
            for (int i = tid; i < SM_X / 4; i += NT) dst[i] = src[i];
        }
        __syncthreads();

        // ---- Phase B: pre[s][v][o] = x[v][:] . W[s][:][o] ----
        #pragma unroll 1
        for (int s = 0; s < NS; ++s) {
            float acc[3][8];
            #pragma unroll
            for (int v = 0; v < 3; ++v)
                #pragma unroll
                for (int j = 0; j < 8; ++j) acc[v][j] = 0.f;

            const float* wb = sW + s * DIN * DOUT + O;
            #pragma unroll 4
            for (int i4 = 0; i4 < DIN / 4; ++i4) {
                float xr[3][4];
                *(float4*)xr[0] = *(const float4*)(sX + v0 * DIN + i4 * 4);
                *(float4*)xr[1] = *(const float4*)(sX + v1 * DIN + i4 * 4);
                *(float4*)xr[2] = *(const float4*)(sX + v2c * DIN + i4 * 4);
                #pragma unroll
                for (int k = 0; k < 4; ++k) {
                    float wr[8];
                    *(float4*)(wr)     = *(const float4*)(wb + (i4 * 4 + k) * DOUT);
                    *(float4*)(wr + 4) = *(const float4*)(wb + (i4 * 4 + k) * DOUT + 4);
                    #pragma unroll
                    for (int v = 0; v < 3; ++v)
                        #pragma unroll
                        for (int j = 0; j < 8; ++j)
                            acc[v][j] += xr[v][k] * wr[j];
                }
            }
            float* pb = sPre + s * V * DOUT + O;
            *(float4*)(pb + v0 * DOUT)     = *(float4*)acc[0];
            *(float4*)(pb + v0 * DOUT + 4) = *(float4*)(acc[0] + 4);
            *(float4*)(pb + v1 * DOUT)     = *(float4*)acc[1];
            *(float4*)(pb + v1 * DOUT + 4) = *(float4*)(acc[1] + 4);
            if (has3) {
                *(float4*)(pb + v2 * DOUT)     = *(float4*)acc[2];
                *(float4*)(pb + v2 * DOUT + 4) = *(float4*)(acc[2] + 4);
            }
        }
        __syncthreads();

        // ---- Phase C: out[u][o] = relu(bias[o] + sum_s adj[s][u][:] . pre[s][:][o]) ----
        {
            float acc[3][8];
            #pragma unroll
            for (int v = 0; v < 3; ++v) {
                *(float4*)acc[v]       = *(const float4*)(sB + O);
                *(float4*)(acc[v] + 4) = *(const float4*)(sB + O + 4);
            }
            #pragma unroll 1
            for (int s = 0; s < NS; ++s) {
                const float* ab = sAdj + s * V * V;
                const float* pb = sPre + s * V * DOUT + O;
                #pragma unroll 4
                for (int vp = 0; vp < V; ++vp) {
                    float a0 = ab[v0 * V + vp];
                    float a1 = ab[v1 * V + vp];
                    float a2 = ab[v2c * V + vp];
                    float pr[8];
                    *(float4*)pr       = *(const float4*)(pb + vp * DOUT);
                    *(float4*)(pr + 4) = *(const float4*)(pb + vp * DOUT + 4);
                    #pragma unroll
                    for (int j = 0; j < 8; ++j) {
                        acc[0][j] += a0 * pr[j];
                        acc[1][j] += a1 * pr[j];
                        acc[2][j] += a2 * pr[j];
                    }
                }
            }
            #pragma unroll
            for (int v = 0; v < 3; ++v)
                #pragma unroll
                for (int j = 0; j < 8; ++j)
                    acc[v][j] = fmaxf(acc[v][j], 0.f);

            float* ob = gout + (size_t)b * V * DOUT + O;
            *(float4*)(ob + v0 * DOUT)     = *(float4*)acc[0];
            *(float4*)(ob + v0 * DOUT + 4) = *(float4*)(acc[0] + 4);
            *(float4*)(ob + v1 * DOUT)     = *(float4*)acc[1];
            *(float4*)(ob + v1 * DOUT + 4) = *(float4*)(acc[1] + 4);
            if (has3) {
                *(float4*)(ob + v2 * DOUT)     = *(float4*)acc[2];
                *(float4*)(ob + v2 * DOUT + 4) = *(float4*)(acc[2] + 4);
            }
        }
        __syncthreads();
    }
}

extern "C" void kernel_launch(void* const* d_in, const int* in_sizes, int n_in,
                              void* d_out, int out_size) {
    const float* x   = (const float*)d_in[0];
    const float* adj = (const float*)d_in[1];
    const float* W   = (const float*)d_in[2];
    const float* bia = (const float*)d_in[3];
    float* out = (float*)d_out;

    cudaFuncSetAttribute(lgconv_kernel,
                         cudaFuncAttributeMaxDynamicSharedMemorySize, SMEM_BYTES);
    lgconv_kernel<<<BTOT / GB, NT, SMEM_BYTES>>>(x, adj, W, bia, out);
}

// round 3
// speedup vs baseline: 2.3916x; 2.3916x over previous
#include <cuda_runtime.h>
#include <cstdint>

// LocalGConv via mma.sync tf32 (3xtf32 for fp32-grade accuracy):
//   pre_s = x_b @ W_s ; out_b = relu(sum_s adj_s @ pre_s + bias)
// B=32768, V=43 (pad 48), DIN=DOUT=64, S=2.
// One warp owns one batch; 4 warps/CTA; W/adj shared in SMEM, x/pre warp-private.

#define NT   128
#define GRID 2048
#define IT   4
#define NV   43

// SMEM float offsets
#define W_OFF   0              // [2][64 rows(i)][stride 72] cols = o
#define ADJ_OFF 9216           // [48 rows(u)][stride 100] cols = s*48+v
#define X_OFF   14016          // per warp: [48 rows(v)][stride 68] cols = i
#define XW      3264
#define PRE_OFF 27072          // per warp: [96 rows(s*48+v)][stride 72] cols = o
#define PW      6912
#define SMEM_FLOATS 54720
#define SMEM_BYTES  (SMEM_FLOATS * 4)

static __device__ __forceinline__ void mma8(float* d, const uint32_t* a, const uint32_t* b) {
    asm volatile(
        "mma.sync.aligned.m16n8k8.row.col.f32.tf32.tf32.f32 "
        "{%0,%1,%2,%3},{%4,%5,%6,%7},{%8,%9},{%0,%1,%2,%3};"
        : "+f"(d[0]), "+f"(d[1]), "+f"(d[2]), "+f"(d[3])
        : "r"(a[0]), "r"(a[1]), "r"(a[2]), "r"(a[3]), "r"(b[0]), "r"(b[1]));
}
static __device__ __forceinline__ uint32_t hi_bits(float f) {
    return __float_as_uint(f) & 0xffffe000u;
}
// split fp32 -> (hi tf32-exact, lo tf32-exact residual)
static __device__ __forceinline__ void split1(float f, uint32_t& h, uint32_t& l) {
    h = hi_bits(f);
    l = __float_as_uint(f - __uint_as_float(h));
}

__global__ __launch_bounds__(NT, 1)
void lgconv_mma(const float* __restrict__ gx, const float* __restrict__ gadj,
                const float* __restrict__ gw, const float* __restrict__ gb,
                float* __restrict__ gout)
{
    extern __shared__ float sm[];
    const int tid = threadIdx.x, w = tid >> 5, lane = tid & 31;
    const int g = lane >> 2, t = lane & 3;

    // ---- prologue: W, adj (zero + fill), x pad rows, bias ----
    for (int i = tid; i < 2 * 64 * 64; i += NT) {
        int s = i >> 12, r = (i >> 6) & 63, o = i & 63;
        sm[W_OFF + s * 4608 + r * 72 + o] = gw[i];
    }
    for (int i = tid; i < 48 * 100; i += NT) sm[ADJ_OFF + i] = 0.f;
    for (int i = tid; i < 4 * 5 * 68; i += NT) {
        int ww = i / 340, r = i % 340;
        sm[X_OFF + ww * XW + (43 + r / 68) * 68 + (r % 68)] = 0.f;
    }
    __syncthreads();
    for (int i = tid; i < 2 * NV * NV; i += NT) {
        int s = i / (NV * NV), r = i % (NV * NV);
        sm[ADJ_OFF + (r / NV) * 100 + s * 48 + (r % NV)] = gadj[i];
    }
    float2 bias2[8];
    #pragma unroll
    for (int nt = 0; nt < 8; ++nt) bias2[nt] = *(const float2*)(gb + nt * 8 + 2 * t);
    __syncthreads();

    float* sX = sm + X_OFF + w * XW;
    float* sP = sm + PRE_OFF + w * PW;
    const float* sW = sm + W_OFF;
    const float* sA = sm + ADJ_OFF;

    for (int it = 0; it < IT; ++it) {
        const size_t b = ((size_t)blockIdx.x * 4 + w) * IT + it;

        // ---- load x_b (43x64) into warp-private SMEM ----
        {
            const float4* src = (const float4*)(gx + b * (NV * 64));
            for (int j = lane; j < NV * 16; j += 32) {
                float4 v = src[j];
                *(float4*)(sX + (j >> 4) * 68 + (j & 15) * 4) = v;
            }
        }
        __syncwarp();

        // ---- Phase B: pre[s][v][o] = x @ W_s  (M=48,N=64,K=64), 3xtf32 ----
        #pragma unroll 1
        for (int s = 0; s < 2; ++s) {
            float acc[3][8][4];
            #pragma unroll
            for (int mt = 0; mt < 3; ++mt)
                #pragma unroll
                for (int nt = 0; nt < 8; ++nt)
                    #pragma unroll
                    for (int j = 0; j < 4; ++j) acc[mt][nt][j] = 0.f;

            #pragma unroll 1
            for (int kt = 0; kt < 8; ++kt) {
                uint32_t ah[3][4], al[3][4];
                #pragma unroll
                for (int mt = 0; mt < 3; ++mt) {
                    const int r0 = mt * 16 + g, c0 = kt * 8 + t;
                    split1(sX[r0 * 68 + c0],       ah[mt][0], al[mt][0]);
                    split1(sX[(r0 + 8) * 68 + c0], ah[mt][1], al[mt][1]);
                    split1(sX[r0 * 68 + c0 + 4],   ah[mt][2], al[mt][2]);
                    split1(sX[(r0 + 8) * 68 + c0 + 4], ah[mt][3], al[mt][3]);
                }
                uint32_t bh[8][2], bl[8][2];
                #pragma unroll
                for (int nt = 0; nt < 8; ++nt) {
                    const float* wp = sW + s * 4608 + (kt * 8 + t) * 72 + nt * 8 + g;
                    split1(wp[0],       bh[nt][0], bl[nt][0]);
                    split1(wp[4 * 72],  bh[nt][1], bl[nt][1]);
                }
                #pragma unroll
                for (int mt = 0; mt < 3; ++mt)
                    #pragma unroll
                    for (int nt = 0; nt < 8; ++nt) {
                        mma8(acc[mt][nt], ah[mt], bh[nt]);
                        mma8(acc[mt][nt], al[mt], bh[nt]);
                        mma8(acc[mt][nt], ah[mt], bl[nt]);
                    }
            }
            // store pre_s (rows 43..47 are exact zeros since x pad rows are 0)
            #pragma unroll
            for (int mt = 0; mt < 3; ++mt)
                #pragma unroll
                for (int nt = 0; nt < 8; ++nt) {
                    const int r0 = s * 48 + mt * 16 + g;
                    *(float2*)(sP + r0 * 72 + nt * 8 + 2 * t) =
                        make_float2(acc[mt][nt][0], acc[mt][nt][1]);
                    *(float2*)(sP + (r0 + 8) * 72 + nt * 8 + 2 * t) =
                        make_float2(acc[mt][nt][2], acc[mt][nt][3]);
                }
        }
        __syncwarp();

        // ---- Phase C: out[u][o] = bias + adjcat @ pre  (M=48,N=64,K=96), 3xtf32 ----
        float oc[3][8][4];
        #pragma unroll
        for (int mt = 0; mt < 3; ++mt)
            #pragma unroll
            for (int nt = 0; nt < 8; ++nt) {
                oc[mt][nt][0] = bias2[nt].x; oc[mt][nt][1] = bias2[nt].y;
                oc[mt][nt][2] = bias2[nt].x; oc[mt][nt][3] = bias2[nt].y;
            }
        #pragma unroll 1
        for (int kt = 0; kt < 12; ++kt) {
            uint32_t ah[3][4], al[3][4];
            #pragma unroll
            for (int mt = 0; mt < 3; ++mt) {
                const int r0 = mt * 16 + g, c0 = kt * 8 + t;
                split1(sA[r0 * 100 + c0],           ah[mt][0], al[mt][0]);
                split1(sA[(r0 + 8) * 100 + c0],     ah[mt][1], al[mt][1]);
                split1(sA[r0 * 100 + c0 + 4],       ah[mt][2], al[mt][2]);
                split1(sA[(r0 + 8) * 100 + c0 + 4], ah[mt][3], al[mt][3]);
            }
            uint32_t bh[8][2], bl[8][2];
            #pragma unroll
            for (int nt = 0; nt < 8; ++nt) {
                const float* pp = sP + (kt * 8 + t) * 72 + nt * 8 + g;
                split1(pp[0],      bh[nt][0], bl[nt][0]);
                split1(pp[4 * 72], bh[nt][1], bl[nt][1]);
            }
            #pragma unroll
            for (int mt = 0; mt < 3; ++mt)
                #pragma unroll
                for (int nt = 0; nt < 8; ++nt) {
                    mma8(oc[mt][nt], ah[mt], bh[nt]);
                    mma8(oc[mt][nt], al[mt], bh[nt]);
                    mma8(oc[mt][nt], ah[mt], bl[nt]);
                }
        }

        // ---- epilogue: relu + store ----
        {
            float* op = gout + b * (NV * 64);
            #pragma unroll
            for (int mt = 0; mt < 3; ++mt)
                #pragma unroll
                for (int nt = 0; nt < 8; ++nt) {
                    const int r0 = mt * 16 + g;
                    *(float2*)(op + r0 * 64 + nt * 8 + 2 * t) =
                        make_float2(fmaxf(oc[mt][nt][0], 0.f), fmaxf(oc[mt][nt][1], 0.f));
                    const int r1 = r0 + 8;
                    if (r1 < NV)
                        *(float2*)(op + r1 * 64 + nt * 8 + 2 * t) =
                            make_float2(fmaxf(oc[mt][nt][2], 0.f), fmaxf(oc[mt][nt][3], 0.f));
                }
        }
        __syncwarp();
    }
}

extern "C" void kernel_launch(void* const* d_in, const int* in_sizes, int n_in,
                              void* d_out, int out_size) {
    const float* x   = (const float*)d_in[0];
    const float* adj = (const float*)d_in[1];
    const float* W   = (const float*)d_in[2];
    const float* b   = (const float*)d_in[3];
    float* out = (float*)d_out;

    cudaFuncSetAttribute(lgconv_mma, cudaFuncAttributeMaxDynamicSharedMemorySize, SMEM_BYTES);
    lgconv_mma<<<GRID, NT, SMEM_BYTES>>>(x, adj, W, b, out);
}

// round 4
// speedup vs baseline: 2.6612x; 1.1127x over previous
#include <cuda_runtime.h>
#include <cstdint>

// LocalGConv via mma.sync tf32 (3xtf32):
//   pre_s = x_b @ W_s ; out_b = relu(sum_s adj_s @ pre_s + bias)
// B=32768, V=43 (pad 48), DIN=DOUT=64, S=2.
// 512 threads = 16 warps = 4 groups. Each group owns one batch; the 4 warps of a
// group each own 16 o-columns end-to-end (pre slice is warp-private).

#define NT   512
#define GRID 2048
#define IT   4
#define NV   43

// SMEM float offsets
#define W_OFF   0              // [2][64 rows(i)][stride 72], cols = o
#define ADJ_OFF 9216           // [48 rows(u)][stride 100], cols = s*48+v (zero padded)
#define X_OFF   14016          // per group: [48 rows(v)][stride 68]
#define XW      3264
#define PRE_OFF 27072          // per group: [96 rows(s*48+v)][stride 72], cols = o
#define PW      6912
#define SMEM_FLOATS 54720
#define SMEM_BYTES  (SMEM_FLOATS * 4)

static __device__ __forceinline__ void mma8(float* d, const uint32_t* a, const uint32_t* b) {
    asm volatile(
        "mma.sync.aligned.m16n8k8.row.col.f32.tf32.tf32.f32 "
        "{%0,%1,%2,%3},{%4,%5,%6,%7},{%8,%9},{%0,%1,%2,%3};"
        : "+f"(d[0]), "+f"(d[1]), "+f"(d[2]), "+f"(d[3])
        : "r"(a[0]), "r"(a[1]), "r"(a[2]), "r"(a[3]), "r"(b[0]), "r"(b[1]));
}
static __device__ __forceinline__ void split1(float f, uint32_t& h, uint32_t& l) {
    h = __float_as_uint(f) & 0xffffe000u;
    l = __float_as_uint(f - __uint_as_float(h));
}
static __device__ __forceinline__ void barg(int bid) {
    asm volatile("bar.sync %0, 128;" :: "r"(bid) : "memory");
}

__global__ __launch_bounds__(NT, 1)
void lgconv_mma(const float* __restrict__ gx, const float* __restrict__ gadj,
                const float* __restrict__ gw, const float* __restrict__ gb,
                float* __restrict__ gout)
{
    extern __shared__ float sm[];
    const int tid = threadIdx.x, wid = tid >> 5, lane = tid & 31;
    const int g = lane >> 2, t = lane & 3;
    const int grp = wid >> 2;          // batch group 0..3
    const int wo  = wid & 3;           // o-slice: cols [wo*16, wo*16+16)
    const int gtid = tid & 127;        // thread id within group

    // ---- prologue: W, adj (zero + fill), x pad rows ----
    for (int i = tid; i < 2 * 64 * 64; i += NT) {
        int s = i >> 12, r = (i >> 6) & 63, o = i & 63;
        sm[W_OFF + s * 4608 + r * 72 + o] = gw[i];
    }
    for (int i = tid; i < 48 * 100; i += NT) sm[ADJ_OFF + i] = 0.f;
    for (int i = tid; i < 4 * 5 * 68; i += NT) {
        int gg = i / 340, r = i % 340;
        sm[X_OFF + gg * XW + (NV + r / 68) * 68 + (r % 68)] = 0.f;
    }
    __syncthreads();
    for (int i = tid; i < 2 * NV * NV; i += NT) {
        int s = i / (NV * NV), r = i % (NV * NV);
        sm[ADJ_OFF + (r / NV) * 100 + s * 48 + (r % NV)] = gadj[i];
    }
    float2 bias2[2];
    #pragma unroll
    for (int nt = 0; nt < 2; ++nt)
        bias2[nt] = *(const float2*)(gb + wo * 16 + nt * 8 + 2 * t);
    __syncthreads();

    float* sX = sm + X_OFF + grp * XW;
    float* sP = sm + PRE_OFF + grp * PW;
    const float* sW = sm + W_OFF;
    const float* sA = sm + ADJ_OFF;
    const int bar = grp + 1;

    for (int it = 0; it < IT; ++it) {
        const size_t b = ((size_t)blockIdx.x * 4 + grp) * IT + it;

        // ---- group-cooperative load of x_b (43x64) ----
        barg(bar);  // previous iteration's readers done
        {
            const float4* src = (const float4*)(gx + b * (NV * 64));
            for (int j = gtid; j < NV * 16; j += 128)
                *(float4*)(sX + (j >> 4) * 68 + (j & 15) * 4) = src[j];
        }
        barg(bar);

        // ---- Phase B: pre[s][v][own o] = x @ W_s  (M=48,N=16,K=64), 3xtf32 ----
        #pragma unroll 1
        for (int s = 0; s < 2; ++s) {
            float acc[3][2][4];
            #pragma unroll
            for (int mt = 0; mt < 3; ++mt)
                #pragma unroll
                for (int nt = 0; nt < 2; ++nt)
                    #pragma unroll
                    for (int j = 0; j < 4; ++j) acc[mt][nt][j] = 0.f;

            #pragma unroll 1
            for (int kt = 0; kt < 8; ++kt) {
                uint32_t ah[3][4], al[3][4];
                #pragma unroll
                for (int mt = 0; mt < 3; ++mt) {
                    const int r0 = mt * 16 + g, c0 = kt * 8 + t;
                    split1(sX[r0 * 68 + c0],           ah[mt][0], al[mt][0]);
                    split1(sX[(r0 + 8) * 68 + c0],     ah[mt][1], al[mt][1]);
                    split1(sX[r0 * 68 + c0 + 4],       ah[mt][2], al[mt][2]);
                    split1(sX[(r0 + 8) * 68 + c0 + 4], ah[mt][3], al[mt][3]);
                }
                uint32_t bh[2][2], bl[2][2];
                #pragma unroll
                for (int nt = 0; nt < 2; ++nt) {
                    const float* wp = sW + s * 4608 + (kt * 8 + t) * 72 + wo * 16 + nt * 8 + g;
                    split1(wp[0],      bh[nt][0], bl[nt][0]);
                    split1(wp[4 * 72], bh[nt][1], bl[nt][1]);
                }
                #pragma unroll
                for (int mt = 0; mt < 3; ++mt)
                    #pragma unroll
                    for (int nt = 0; nt < 2; ++nt) {
                        mma8(acc[mt][nt], ah[mt], bh[nt]);
                        mma8(acc[mt][nt], al[mt], bh[nt]);
                        mma8(acc[mt][nt], ah[mt], bl[nt]);
                    }
            }
            #pragma unroll
            for (int mt = 0; mt < 3; ++mt)
                #pragma unroll
                for (int nt = 0; nt < 2; ++nt) {
                    const int r0 = s * 48 + mt * 16 + g;
                    const int c = wo * 16 + nt * 8 + 2 * t;
                    *(float2*)(sP + r0 * 72 + c) =
                        make_float2(acc[mt][nt][0], acc[mt][nt][1]);
                    *(float2*)(sP + (r0 + 8) * 72 + c) =
                        make_float2(acc[mt][nt][2], acc[mt][nt][3]);
                }
        }
        __syncwarp();  // pre slice is warp-private: warp-level store->load fence only

        // ---- Phase C: out[u][own o] = bias + adjcat @ pre  (M=48,N=16,K=96) ----
        float oc[3][2][4];
        #pragma unroll
        for (int mt = 0; mt < 3; ++mt)
            #pragma unroll
            for (int nt = 0; nt < 2; ++nt) {
                oc[mt][nt][0] = bias2[nt].x; oc[mt][nt][1] = bias2[nt].y;
                oc[mt][nt][2] = bias2[nt].x; oc[mt][nt][3] = bias2[nt].y;
            }
        #pragma unroll 1
        for (int kt = 0; kt < 12; ++kt) {
            uint32_t ah[3][4], al[3][4];
            #pragma unroll
            for (int mt = 0; mt < 3; ++mt) {
                const int r0 = mt * 16 + g, c0 = kt * 8 + t;
                split1(sA[r0 * 100 + c0],           ah[mt][0], al[mt][0]);
                split1(sA[(r0 + 8) * 100 + c0],     ah[mt][1], al[mt][1]);
                split1(sA[r0 * 100 + c0 + 4],       ah[mt][2], al[mt][2]);
                split1(sA[(r0 + 8) * 100 + c0 + 4], ah[mt][3], al[mt][3]);
            }
            uint32_t bh[2][2], bl[2][2];
            #pragma unroll
            for (int nt = 0; nt < 2; ++nt) {
                const float* pp = sP + (kt * 8 + t) * 72 + wo * 16 + nt * 8 + g;
                split1(pp[0],      bh[nt][0], bl[nt][0]);
                split1(pp[4 * 72], bh[nt][1], bl[nt][1]);
            }
            #pragma unroll
            for (int mt = 0; mt < 3; ++mt)
                #pragma unroll
                for (int nt = 0; nt < 2; ++nt) {
                    mma8(oc[mt][nt], ah[mt], bh[nt]);
                    mma8(oc[mt][nt], al[mt], bh[nt]);
                    mma8(oc[mt][nt], ah[mt], bl[nt]);
                }
        }

        // ---- epilogue: relu + store own 16 o-columns ----
        {
            float* op = gout + b * (NV * 64) + wo * 16;
            #pragma unroll
            for (int mt = 0; mt < 3; ++mt)
                #pragma unroll
                for (int nt = 0; nt < 2; ++nt) {
                    const int r0 = mt * 16 + g, c = nt * 8 + 2 * t;
                    *(float2*)(op + r0 * 64 + c) =
                        make_float2(fmaxf(oc[mt][nt][0], 0.f), fmaxf(oc[mt][nt][1], 0.f));
                    const int r1 = r0 + 8;
                    if (r1 < NV)
                        *(float2*)(op + r1 * 64 + c) =
                            make_float2(fmaxf(oc[mt][nt][2], 0.f), fmaxf(oc[mt][nt][3], 0.f));
                }
        }
    }
}

extern "C" void kernel_launch(void* const* d_in, const int* in_sizes, int n_in,
                              void* d_out, int out_size) {
    const float* x   = (const float*)d_in[0];
    const float* adj = (const float*)d_in[1];
    const float* W   = (const float*)d_in[2];
    const float* b   = (const float*)d_in[3];
    float* out = (float*)d_out;

    cudaFuncSetAttribute(lgconv_mma, cudaFuncAttributeMaxDynamicSharedMemorySize, SMEM_BYTES);
    lgconv_mma<<<GRID, NT, SMEM_BYTES>>>(x, adj, W, b, out);
}

// round 5
// speedup vs baseline: 3.8160x; 1.4339x over previous
#include <cuda_runtime.h>
#include <cuda_bf16.h>
#include <cstdint>

// LocalGConv via mma.sync bf16 m16n8k16 (3xbf16 split for accuracy):
//   pre_s = x_b @ W_s ; out_b = relu(sum_s adj_s @ pre_s + bias)
// B=32768, V=43 (pad 48), DIN=DOUT=64, S=2.
// 512 threads = 16 warps = 4 groups; each group owns one batch; warps of a group
// own 16 o-columns end-to-end. All operands pre-split into packed bf16 hi/lo SMEM.

#define NT   512
#define GRID 2048
#define IT   4
#define NV   43

// SMEM word (uint32) offsets
#define WH_OFF   0          // [2][64 o rows][36 iw stride] (iw = i/2 pairs)
#define WL_OFF   4608
#define ADJH_OFF 9216       // [48 u rows][52 stride], vw = (s*48+v)/2 in 0..47
#define ADJL_OFF 11712
#define GRP_OFF  14208
#define XH_G     0          // per group: [48 v rows][36 iw stride]
#define XL_G     1728
#define PREH_G   3456       // per group: [48 vpair rows][72 o stride]
#define PREL_G   6912
#define GRP_W    10368
#define SMEM_WORDS (GRP_OFF + 4*GRP_W + 64)
#define SMEM_BYTES (SMEM_WORDS * 4)     // 222,976 B

static __device__ __forceinline__ void mma16(float* d, const uint32_t* a, const uint32_t* b) {
    asm volatile(
        "mma.sync.aligned.m16n8k16.row.col.f32.bf16.bf16.f32 "
        "{%0,%1,%2,%3},{%4,%5,%6,%7},{%8,%9},{%0,%1,%2,%3};"
        : "+f"(d[0]), "+f"(d[1]), "+f"(d[2]), "+f"(d[3])
        : "r"(a[0]), "r"(a[1]), "r"(a[2]), "r"(a[3]), "r"(b[0]), "r"(b[1]));
}
static __device__ __forceinline__ void bsplit(float f, uint16_t& h, uint16_t& l) {
    __nv_bfloat16 bh = __float2bfloat16_rn(f);
    float r = f - __bfloat162float(bh);
    __nv_bfloat16 bl = __float2bfloat16_rn(r);
    h = *(uint16_t*)&bh;
    l = *(uint16_t*)&bl;
}
static __device__ __forceinline__ void barg(int bid) {
    asm volatile("bar.sync %0, 128;" :: "r"(bid) : "memory");
}

__global__ __launch_bounds__(NT, 1)
void lgconv_bf16(const float* __restrict__ gx, const float* __restrict__ gadj,
                 const float* __restrict__ gw, const float* __restrict__ gb,
                 float* __restrict__ gout)
{
    extern __shared__ uint32_t sm[];
    uint16_t* sh = (uint16_t*)sm;
    const int tid = threadIdx.x, wid = tid >> 5, lane = tid & 31;
    const int g = lane >> 2, t = lane & 3;
    const int grp = wid >> 2, wo = wid & 3, gtid = tid & 127;

    // ---- prologue: split W and adj into packed bf16 hi/lo (constant all kernel) ----
    for (int i = tid; i < 48 * 52; i += NT) { sm[ADJH_OFF + i] = 0; sm[ADJL_OFF + i] = 0; }
    for (int i = tid; i < 4 * 5 * 36; i += NT) {        // x pad rows v=43..47, all groups
        int gg = i / 180, r = i % 180;
        int w = GRP_OFF + gg * GRP_W + (NV + r / 36) * 36 + (r % 36);
        sm[w + XH_G] = 0; sm[w + XL_G] = 0;
    }
    for (int idx = tid; idx < 2 * 64 * 64; idx += NT) { // gw [s][i][o]
        int s = idx >> 12, i = (idx >> 6) & 63, o = idx & 63;
        uint16_t h, l; bsplit(gw[idx], h, l);
        int w = (s * 64 + o) * 36 + (i >> 1), hf = i & 1;
        sh[(WH_OFF + w) * 2 + hf] = h;
        sh[(WL_OFF + w) * 2 + hf] = l;
    }
    __syncthreads();
    for (int idx = tid; idx < 2 * NV * NV; idx += NT) { // gadj [s][u][v]
        int s = idx / (NV * NV), r = idx % (NV * NV), u = r / NV, v = r % NV;
        uint16_t h, l; bsplit(gadj[idx], h, l);
        int w = u * 52 + s * 24 + (v >> 1), hf = v & 1;
        sh[(ADJH_OFF + w) * 2 + hf] = h;
        sh[(ADJL_OFF + w) * 2 + hf] = l;
    }
    float2 bias2[2];
    #pragma unroll
    for (int nt = 0; nt < 2; ++nt)
        bias2[nt] = *(const float2*)(gb + wo * 16 + nt * 8 + 2 * t);
    __syncthreads();

    uint32_t* xh = sm + GRP_OFF + grp * GRP_W + XH_G;
    uint32_t* xl = sm + GRP_OFF + grp * GRP_W + XL_G;
    uint32_t* ph = sm + GRP_OFF + grp * GRP_W + PREH_G;
    uint32_t* pl = sm + GRP_OFF + grp * GRP_W + PREL_G;
    const uint32_t* sWh = sm + WH_OFF;
    const uint32_t* sWl = sm + WL_OFF;
    const uint32_t* sAh = sm + ADJH_OFF;
    const uint32_t* sAl = sm + ADJL_OFF;
    const int bar = grp + 1;

    for (int it = 0; it < IT; ++it) {
        const size_t b = ((size_t)blockIdx.x * 4 + grp) * IT + it;

        // ---- group-cooperative x load + bf16 hi/lo split ----
        barg(bar);
        {
            const float4* src = (const float4*)(gx + b * (NV * 64));
            for (int j = gtid; j < NV * 16; j += 128) {
                float4 f = src[j];
                int w = (j >> 4) * 36 + (j & 15) * 2;
                uint16_t h0,l0,h1,l1,h2,l2,h3,l3;
                bsplit(f.x,h0,l0); bsplit(f.y,h1,l1); bsplit(f.z,h2,l2); bsplit(f.w,h3,l3);
                xh[w]     = (uint32_t)h0 | ((uint32_t)h1 << 16);
                xh[w + 1] = (uint32_t)h2 | ((uint32_t)h3 << 16);
                xl[w]     = (uint32_t)l0 | ((uint32_t)l1 << 16);
                xl[w + 1] = (uint32_t)l2 | ((uint32_t)l3 << 16);
            }
        }
        barg(bar);

        // ---- Phase B: pre[s][v][own o] = x @ W_s  (M=48,N=16,K=64) ----
        {
            float acc[2][3][2][4];
            #pragma unroll
            for (int s = 0; s < 2; ++s)
                #pragma unroll
                for (int mt = 0; mt < 3; ++mt)
                    #pragma unroll
                    for (int nt = 0; nt < 2; ++nt)
                        #pragma unroll
                        for (int j = 0; j < 4; ++j) acc[s][mt][nt][j] = 0.f;

            #pragma unroll 1
            for (int kt = 0; kt < 4; ++kt) {
                uint32_t ah[3][4], al[3][4];
                const int c = kt * 8 + t;
                #pragma unroll
                for (int mt = 0; mt < 3; ++mt) {
                    const int r0 = (mt * 16 + g) * 36, r8 = r0 + 8 * 36;
                    ah[mt][0] = xh[r0 + c];     ah[mt][1] = xh[r8 + c];
                    ah[mt][2] = xh[r0 + c + 4]; ah[mt][3] = xh[r8 + c + 4];
                    al[mt][0] = xl[r0 + c];     al[mt][1] = xl[r8 + c];
                    al[mt][2] = xl[r0 + c + 4]; al[mt][3] = xl[r8 + c + 4];
                }
                #pragma unroll
                for (int s = 0; s < 2; ++s)
                    #pragma unroll
                    for (int nt = 0; nt < 2; ++nt) {
                        const int wr = (s * 64 + wo * 16 + nt * 8 + g) * 36 + c;
                        uint32_t bh[2] = { sWh[wr], sWh[wr + 4] };
                        uint32_t bl[2] = { sWl[wr], sWl[wr + 4] };
                        #pragma unroll
                        for (int mt = 0; mt < 3; ++mt) {
                            mma16(acc[s][mt][nt], ah[mt], bh);
                            mma16(acc[s][mt][nt], al[mt], bh);
                            mma16(acc[s][mt][nt], ah[mt], bl);
                        }
                    }
            }
            // store pre as packed bf16 hi/lo (pairs along v)
            #pragma unroll
            for (int s = 0; s < 2; ++s)
                #pragma unroll
                for (int mt = 0; mt < 3; ++mt)
                    #pragma unroll
                    for (int nt = 0; nt < 2; ++nt) {
                        const int vp0 = s * 24 + mt * 8 + (g >> 1), hf = g & 1;
                        const int o0 = wo * 16 + nt * 8 + 2 * t;
                        uint16_t h, l;
                        bsplit(acc[s][mt][nt][0], h, l);
                        sh[(PREH_G ? 0 : 0) + ((ph - sm) + vp0 * 72 + o0) * 2 + hf] = h;
                        sh[((pl - sm) + vp0 * 72 + o0) * 2 + hf] = l;
                        bsplit(acc[s][mt][nt][1], h, l);
                        sh[((ph - sm) + vp0 * 72 + o0 + 1) * 2 + hf] = h;
                        sh[((pl - sm) + vp0 * 72 + o0 + 1) * 2 + hf] = l;
                        bsplit(acc[s][mt][nt][2], h, l);
                        sh[((ph - sm) + (vp0 + 4) * 72 + o0) * 2 + hf] = h;
                        sh[((pl - sm) + (vp0 + 4) * 72 + o0) * 2 + hf] = l;
                        bsplit(acc[s][mt][nt][3], h, l);
                        sh[((ph - sm) + (vp0 + 4) * 72 + o0 + 1) * 2 + hf] = h;
                        sh[((pl - sm) + (vp0 + 4) * 72 + o0 + 1) * 2 + hf] = l;
                    }
        }
        __syncwarp();   // pre columns are warp-private

        // ---- Phase C: out[u][own o] = bias + adjcat @ pre  (M=48,N=16,K=96) ----
        float oc[3][2][4];
        #pragma unroll
        for (int mt = 0; mt < 3; ++mt)
            #pragma unroll
            for (int nt = 0; nt < 2; ++nt) {
                oc[mt][nt][0] = bias2[nt].x; oc[mt][nt][1] = bias2[nt].y;
                oc[mt][nt][2] = bias2[nt].x; oc[mt][nt][3] = bias2[nt].y;
            }
        #pragma unroll 1
        for (int kt = 0; kt < 6; ++kt) {
            uint32_t ah[3][4], al[3][4];
            const int c = kt * 8 + t;
            #pragma unroll
            for (int mt = 0; mt < 3; ++mt) {
                const int r0 = (mt * 16 + g) * 52, r8 = r0 + 8 * 52;
                ah[mt][0] = sAh[r0 + c];     ah[mt][1] = sAh[r8 + c];
                ah[mt][2] = sAh[r0 + c + 4]; ah[mt][3] = sAh[r8 + c + 4];
                al[mt][0] = sAl[r0 + c];     al[mt][1] = sAl[r8 + c];
                al[mt][2] = sAl[r0 + c + 4]; al[mt][3] = sAl[r8 + c + 4];
            }
            #pragma unroll
            for (int nt = 0; nt < 2; ++nt) {
                const int pr = c * 72 + wo * 16 + nt * 8 + g;
                uint32_t bh[2] = { ph[pr], ph[pr + 4 * 72] };
                uint32_t bl[2] = { pl[pr], pl[pr + 4 * 72] };
                #pragma unroll
                for (int mt = 0; mt < 3; ++mt) {
                    mma16(oc[mt][nt], ah[mt], bh);
                    mma16(oc[mt][nt], al[mt], bh);
                    mma16(oc[mt][nt], ah[mt], bl);
                }
            }
        }

        // ---- epilogue: relu + store own 16 o-columns ----
        {
            float* op = gout + b * (NV * 64) + wo * 16;
            #pragma unroll
            for (int mt = 0; mt < 3; ++mt)
                #pragma unroll
                for (int nt = 0; nt < 2; ++nt) {
                    const int r0 = mt * 16 + g, c = nt * 8 + 2 * t;
                    *(float2*)(op + r0 * 64 + c) =
                        make_float2(fmaxf(oc[mt][nt][0], 0.f), fmaxf(oc[mt][nt][1], 0.f));
                    const int r1 = r0 + 8;
                    if (r1 < NV)
                        *(float2*)(op + r1 * 64 + c) =
                            make_float2(fmaxf(oc[mt][nt][2], 0.f), fmaxf(oc[mt][nt][3], 0.f));
                }
        }
    }
}

extern "C" void kernel_launch(void* const* d_in, const int* in_sizes, int n_in,
                              void* d_out, int out_size) {
    const float* x   = (const float*)d_in[0];
    const float* adj = (const float*)d_in[1];
    const float* W   = (const float*)d_in[2];
    const float* b   = (const float*)d_in[3];
    float* out = (float*)d_out;

    cudaFuncSetAttribute(lgconv_bf16, cudaFuncAttributeMaxDynamicSharedMemorySize, SMEM_BYTES);
    lgconv_bf16<<<GRID, NT, SMEM_BYTES>>>(x, adj, W, b, out);
}

// round 6
// speedup vs baseline: 4.0975x; 1.0738x over previous
#include <cuda_runtime.h>
#include <cuda_bf16.h>
#include <cstdint>

// LocalGConv via mma.sync bf16 m16n8k16 (3xbf16) + ldmatrix fragment loads:
//   pre_s = x_b @ W_s ; out_b = relu(sum_s adj_s @ pre_s + bias)
// B=32768, V=43 (pad 48), DIN=DOUT=64, S=2.
// 512 threads = 16 warps = 4 groups; group owns a batch; warp owns 16 o-columns.

#define NT   512
#define GRID 2048
#define IT   4
#define NV   43

// SMEM word (uint32) offsets
#define WH_OFF   0          // [s*64+o rows][36 words], word c = k-pair
#define WL_OFF   4608
#define ADJH_OFF 9216       // [48 u rows][52 words], word = s*24 + (v>>1)
#define ADJL_OFF 11712
#define GRP_OFF  14208
#define XH_G     0          // per group: [48 v rows][36 words]
#define XL_G     1728
#define PREH_G   3456       // per group: [64 o rows][52 words], word = s*24+(v>>1)
#define PREL_G   6784
#define GRP_W    10112
#define SMEM_WORDS (GRP_OFF + 4*GRP_W + 32)
#define SMEM_BYTES (SMEM_WORDS * 4)   // 218,752 B

static __device__ __forceinline__ void mma16(float* d, const uint32_t* a, const uint32_t* b) {
    asm volatile(
        "mma.sync.aligned.m16n8k16.row.col.f32.bf16.bf16.f32 "
        "{%0,%1,%2,%3},{%4,%5,%6,%7},{%8,%9},{%0,%1,%2,%3};"
        : "+f"(d[0]), "+f"(d[1]), "+f"(d[2]), "+f"(d[3])
        : "r"(a[0]), "r"(a[1]), "r"(a[2]), "r"(a[3]), "r"(b[0]), "r"(b[1]));
}
static __device__ __forceinline__ void ldsm4(uint32_t* d, uint32_t addr) {
    asm volatile("ldmatrix.sync.aligned.m8n8.x4.shared.b16 {%0,%1,%2,%3}, [%4];"
        : "=r"(d[0]), "=r"(d[1]), "=r"(d[2]), "=r"(d[3]) : "r"(addr));
}
static __device__ __forceinline__ uint32_t su32(const void* p) {
    uint32_t a;
    asm("{ .reg .u64 t; cvta.to.shared.u64 t, %1; cvt.u32.u64 %0, t; }" : "=r"(a) : "l"(p));
    return a;
}
static __device__ __forceinline__ void bsplit(float f, uint16_t& h, uint16_t& l) {
    __nv_bfloat16 bh = __float2bfloat16_rn(f);
    float r = f - __bfloat162float(bh);
    __nv_bfloat16 bl = __float2bfloat16_rn(r);
    h = *(uint16_t*)&bh;
    l = *(uint16_t*)&bl;
}
static __device__ __forceinline__ void barg(int bid) {
    asm volatile("bar.sync %0, 128;" :: "r"(bid) : "memory");
}

__global__ __launch_bounds__(NT, 1)
void lgconv_bf16(const float* __restrict__ gx, const float* __restrict__ gadj,
                 const float* __restrict__ gw, const float* __restrict__ gb,
                 float* __restrict__ gout)
{
    extern __shared__ uint32_t sm[];
    uint16_t* sh = (uint16_t*)sm;
    const uint32_t sb = su32(sm);
    const int tid = threadIdx.x, wid = tid >> 5, lane = tid & 31;
    const int g = lane >> 2, t = lane & 3;
    const int grp = wid >> 2, wo = wid & 3, gtid = tid & 127;
    const int q = lane >> 3, rr = lane & 7;

    // ldmatrix per-lane byte offsets
    // A-map (x stride 36 / adj stride 52): matrices (m0-7,k0),(m8-15,k0),(m0-7,k1),(m8-15,k1)
    const uint32_t aoffX = (uint32_t)((((q & 1) * 8 + rr) * 36 + (q >> 1) * 4) * 4);
    const uint32_t aoffA = (uint32_t)((((q & 1) * 8 + rr) * 52 + (q >> 1) * 4) * 4);
    // B-map (W stride 36 / pre stride 52): matrices (n0-7,k0),(n0-7,k1),(n8-15,k0),(n8-15,k1)
    const uint32_t boffW = (uint32_t)(((wo * 16 + (q >> 1) * 8 + rr) * 36 + (q & 1) * 4) * 4);
    const uint32_t boffP = (uint32_t)(((wo * 16 + (q >> 1) * 8 + rr) * 52 + (q & 1) * 4) * 4);

    // ---- prologue: bf16 hi/lo split of W, adj; zero pads ----
    for (int i = tid; i < 48 * 52; i += NT) { sm[ADJH_OFF + i] = 0; sm[ADJL_OFF + i] = 0; }
    for (int i = tid; i < 4 * 5 * 36; i += NT) {      // x pad rows 43..47, all groups
        int gg = i / 180, r = i % 180;
        int w = GRP_OFF + gg * GRP_W + (NV + r / 36) * 36 + (r % 36);
        sm[w + XH_G] = 0; sm[w + XL_G] = 0;
    }
    for (int idx = tid; idx < 2 * 64 * 64; idx += NT) {   // gw [s][i][o]
        int s = idx >> 12, i = (idx >> 6) & 63, o = idx & 63;
        uint16_t h, l; bsplit(gw[idx], h, l);
        int w = (s * 64 + o) * 36 + (i >> 1), hf = i & 1;
        sh[(WH_OFF + w) * 2 + hf] = h;
        sh[(WL_OFF + w) * 2 + hf] = l;
    }
    __syncthreads();
    for (int idx = tid; idx < 2 * NV * NV; idx += NT) {   // gadj [s][u][v]
        int s = idx / (NV * NV), r = idx % (NV * NV), u = r / NV, v = r % NV;
        uint16_t h, l; bsplit(gadj[idx], h, l);
        int w = u * 52 + s * 24 + (v >> 1), hf = v & 1;
        sh[(ADJH_OFF + w) * 2 + hf] = h;
        sh[(ADJL_OFF + w) * 2 + hf] = l;
    }
    float2 bias2[2];
    #pragma unroll
    for (int nt = 0; nt < 2; ++nt)
        bias2[nt] = *(const float2*)(gb + wo * 16 + nt * 8 + 2 * t);
    __syncthreads();

    // group-local base byte addresses
    const uint32_t xh_b  = sb + (GRP_OFF + grp * GRP_W + XH_G) * 4;
    const uint32_t xl_b  = sb + (GRP_OFF + grp * GRP_W + XL_G) * 4;
    const uint32_t prh_b = sb + (GRP_OFF + grp * GRP_W + PREH_G) * 4;
    const uint32_t prl_b = sb + (GRP_OFF + grp * GRP_W + PREL_G) * 4;
    const uint32_t wh_b  = sb + WH_OFF * 4, wl_b = sb + WL_OFF * 4;
    const uint32_t ah_b  = sb + ADJH_OFF * 4, al_b = sb + ADJL_OFF * 4;
    const int preh_w = GRP_OFF + grp * GRP_W + PREH_G;
    const int prel_w = GRP_OFF + grp * GRP_W + PREL_G;
    uint32_t* xh = sm + GRP_OFF + grp * GRP_W + XH_G;
    uint32_t* xl = sm + GRP_OFF + grp * GRP_W + XL_G;
    const int bar = grp + 1;

    for (int it = 0; it < IT; ++it) {
        const size_t b = ((size_t)blockIdx.x * 4 + grp) * IT + it;

        // ---- group-cooperative x load + bf16 hi/lo split ----
        barg(bar);
        {
            const float4* src = (const float4*)(gx + b * (NV * 64));
            for (int j = gtid; j < NV * 16; j += 128) {
                float4 f = src[j];
                int w = (j >> 4) * 36 + (j & 15) * 2;
                uint16_t h0,l0,h1,l1,h2,l2,h3,l3;
                bsplit(f.x,h0,l0); bsplit(f.y,h1,l1); bsplit(f.z,h2,l2); bsplit(f.w,h3,l3);
                xh[w]     = (uint32_t)h0 | ((uint32_t)h1 << 16);
                xh[w + 1] = (uint32_t)h2 | ((uint32_t)h3 << 16);
                xl[w]     = (uint32_t)l0 | ((uint32_t)l1 << 16);
                xl[w + 1] = (uint32_t)l2 | ((uint32_t)l3 << 16);
            }
        }
        barg(bar);

        // ---- Phase B: pre[s][v][own o] = x @ W_s  (M=48,N=16 per warp,K=64) ----
        {
            float acc[2][3][2][4];
            #pragma unroll
            for (int s = 0; s < 2; ++s)
                #pragma unroll
                for (int mt = 0; mt < 3; ++mt)
                    #pragma unroll
                    for (int nt = 0; nt < 2; ++nt)
                        #pragma unroll
                        for (int j = 0; j < 4; ++j) acc[s][mt][nt][j] = 0.f;

            #pragma unroll 1
            for (int kt = 0; kt < 4; ++kt) {
                uint32_t ah[3][4], al[3][4], bh[2][4], bl[2][4];
                #pragma unroll
                for (int mt = 0; mt < 3; ++mt) {
                    ldsm4(ah[mt], xh_b + (uint32_t)(mt * 16 * 36 * 4) + kt * 32 + aoffX);
                    ldsm4(al[mt], xl_b + (uint32_t)(mt * 16 * 36 * 4) + kt * 32 + aoffX);
                }
                #pragma unroll
                for (int s = 0; s < 2; ++s) {
                    ldsm4(bh[s], wh_b + (uint32_t)(s * 2304 * 4) + kt * 32 + boffW);
                    ldsm4(bl[s], wl_b + (uint32_t)(s * 2304 * 4) + kt * 32 + boffW);
                }
                // split terms as separate passes: same-acc MMAs are 12 apart
                #pragma unroll
                for (int s = 0; s < 2; ++s)
                    #pragma unroll
                    for (int nt = 0; nt < 2; ++nt)
                        #pragma unroll
                        for (int mt = 0; mt < 3; ++mt)
                            mma16(acc[s][mt][nt], ah[mt], &bh[s][nt * 2]);
                #pragma unroll
                for (int s = 0; s < 2; ++s)
                    #pragma unroll
                    for (int nt = 0; nt < 2; ++nt)
                        #pragma unroll
                        for (int mt = 0; mt < 3; ++mt)
                            mma16(acc[s][mt][nt], al[mt], &bh[s][nt * 2]);
                #pragma unroll
                for (int s = 0; s < 2; ++s)
                    #pragma unroll
                    for (int nt = 0; nt < 2; ++nt)
                        #pragma unroll
                        for (int mt = 0; mt < 3; ++mt)
                            mma16(acc[s][mt][nt], ah[mt], &bl[s][nt * 2]);
            }
            // store pre (o-major, packed bf16 pairs along v)
            #pragma unroll
            for (int s = 0; s < 2; ++s)
                #pragma unroll
                for (int mt = 0; mt < 3; ++mt)
                    #pragma unroll
                    for (int nt = 0; nt < 2; ++nt) {
                        const int o0 = wo * 16 + nt * 8 + 2 * t;
                        const int kb = s * 24 + mt * 8 + (g >> 1);
                        #pragma unroll
                        for (int j = 0; j < 4; ++j) {
                            uint16_t h, l; bsplit(acc[s][mt][nt][j], h, l);
                            const int w = (o0 + (j & 1)) * 52 + kb + 4 * (j >> 1);
                            sh[(preh_w + w) * 2 + (g & 1)] = h;
                            sh[(prel_w + w) * 2 + (g & 1)] = l;
                        }
                    }
        }
        __syncwarp();   // pre rows are warp-private

        // ---- Phase C: out[u][own o] = bias + adjcat @ pre  (M=48,N=16,K=96) ----
        float oc[3][2][4];
        #pragma unroll
        for (int mt = 0; mt < 3; ++mt)
            #pragma unroll
            for (int nt = 0; nt < 2; ++nt) {
                oc[mt][nt][0] = bias2[nt].x; oc[mt][nt][1] = bias2[nt].y;
                oc[mt][nt][2] = bias2[nt].x; oc[mt][nt][3] = bias2[nt].y;
            }
        #pragma unroll 1
        for (int kt = 0; kt < 6; ++kt) {
            uint32_t ah[3][4], al[3][4], bp_h[4], bp_l[4];
            #pragma unroll
            for (int mt = 0; mt < 3; ++mt) {
                ldsm4(ah[mt], ah_b + (uint32_t)(mt * 16 * 52 * 4) + kt * 32 + aoffA);
                ldsm4(al[mt], al_b + (uint32_t)(mt * 16 * 52 * 4) + kt * 32 + aoffA);
            }
            ldsm4(bp_h, prh_b + kt * 32 + boffP);
            ldsm4(bp_l, prl_b + kt * 32 + boffP);
            #pragma unroll
            for (int nt = 0; nt < 2; ++nt)
                #pragma unroll
                for (int mt = 0; mt < 3; ++mt)
                    mma16(oc[mt][nt], ah[mt], &bp_h[nt * 2]);
            #pragma unroll
            for (int nt = 0; nt < 2; ++nt)
                #pragma unroll
                for (int mt = 0; mt < 3; ++mt)
                    mma16(oc[mt][nt], al[mt], &bp_h[nt * 2]);
            #pragma unroll
            for (int nt = 0; nt < 2; ++nt)
                #pragma unroll
                for (int mt = 0; mt < 3; ++mt)
                    mma16(oc[mt][nt], ah[mt], &bp_l[nt * 2]);
        }

        // ---- epilogue: relu + store own 16 o-columns ----
        {
            float* op = gout + b * (NV * 64) + wo * 16;
            #pragma unroll
            for (int mt = 0; mt < 3; ++mt)
                #pragma unroll
                for (int nt = 0; nt < 2; ++nt) {
                    const int r0 = mt * 16 + g, c = nt * 8 + 2 * t;
                    *(float2*)(op + r0 * 64 + c) =
                        make_float2(fmaxf(oc[mt][nt][0], 0.f), fmaxf(oc[mt][nt][1], 0.f));
                    const int r1 = r0 + 8;
                    if (r1 < NV)
                        *(float2*)(op + r1 * 64 + c) =
                            make_float2(fmaxf(oc[mt][nt][2], 0.f), fmaxf(oc[mt][nt][3], 0.f));
                }
        }
    }
}

extern "C" void kernel_launch(void* const* d_in, const int* in_sizes, int n_in,
                              void* d_out, int out_size) {
    const float* x   = (const float*)d_in[0];
    const float* adj = (const float*)d_in[1];
    const float* W   = (const float*)d_in[2];
    const float* b   = (const float*)d_in[3];
    float* out = (float*)d_out;

    cudaFuncSetAttribute(lgconv_bf16, cudaFuncAttributeMaxDynamicSharedMemorySize, SMEM_BYTES);
    lgconv_bf16<<<GRID, NT, SMEM_BYTES>>>(x, adj, W, b, out);
}

// round 7
// speedup vs baseline: 5.0284x; 1.2272x over previous
#include <cuda_runtime.h>
#include <cuda_fp16.h>
#include <cstdint>

// LocalGConv, transposed dataflow, fp16 2-term split, pre kept in registers:
//   pre^T = W_s^T @ x^T   (M=16 o-rows per warp, N=48 v, K=64 i)
//   out^T = pre^T @ adj^T (M=16 o-rows, N=48 u, K=96 s,v)
// B=32768, V=43 (pad 48), DIN=DOUT=64, S=2.
// 512 threads = 16 warps = 4 groups; group owns one batch/iter; warp owns 16 o-rows.

#define NT   512
#define GRID 2048
#define IT   4
#define NV   43

// SMEM word offsets
#define WTH_OFF 0        // W^T hi: [s*64+o rows][36 words] (fp16 pairs of i)
#define WTL_OFF 4608     // W^T lo
#define ADJ_OFF 9216     // adj fp16: [48 u rows][52 words] (pairs of k = s*48+v)
#define X_OFF   11712    // per group: [48 v rows][36 words] fp16
#define XW      1728
#define SMEM_WORDS (X_OFF + 4 * XW)
#define SMEM_BYTES (SMEM_WORDS * 4)   // 74,496 B

static __device__ __forceinline__ void mma16(float* d, const uint32_t* a, const uint32_t* b) {
    asm volatile(
        "mma.sync.aligned.m16n8k16.row.col.f32.f16.f16.f32 "
        "{%0,%1,%2,%3},{%4,%5,%6,%7},{%8,%9},{%0,%1,%2,%3};"
        : "+f"(d[0]), "+f"(d[1]), "+f"(d[2]), "+f"(d[3])
        : "r"(a[0]), "r"(a[1]), "r"(a[2]), "r"(a[3]), "r"(b[0]), "r"(b[1]));
}
static __device__ __forceinline__ void ldsm4(uint32_t* d, uint32_t addr) {
    asm volatile("ldmatrix.sync.aligned.m8n8.x4.shared.b16 {%0,%1,%2,%3}, [%4];"
        : "=r"(d[0]), "=r"(d[1]), "=r"(d[2]), "=r"(d[3]) : "r"(addr));
}
static __device__ __forceinline__ uint32_t su32(const void* p) {
    uint32_t a;
    asm("{ .reg .u64 t; cvta.to.shared.u64 t, %1; cvt.u32.u64 %0, t; }" : "=r"(a) : "l"(p));
    return a;
}
// pack: lower 16 = f16(lo), upper 16 = f16(hi)
static __device__ __forceinline__ uint32_t f16x2(float hi, float lo) {
    uint32_t d;
    asm("cvt.rn.f16x2.f32 %0, %1, %2;" : "=r"(d) : "f"(hi), "f"(lo));
    return d;
}
static __device__ __forceinline__ float2 unpack_h2(uint32_t u) {
    __half2 h = *(__half2*)&u;
    return __half22float2(h);   // .x = lo, .y = hi
}
static __device__ __forceinline__ void barg(int bid) {
    asm volatile("bar.sync %0, 128;" :: "r"(bid) : "memory");
}

__global__ __launch_bounds__(NT, 1)
void lgconv_fp16(const float* __restrict__ gx, const float* __restrict__ gadj,
                 const float* __restrict__ gw, const float* __restrict__ gb,
                 float* __restrict__ gout)
{
    extern __shared__ uint32_t sm[];
    uint16_t* shw = (uint16_t*)sm;
    const uint32_t sb = su32(sm);
    const int tid = threadIdx.x, wid = tid >> 5, lane = tid & 31;
    const int g = lane >> 2, t = lane & 3;
    const int grp = wid >> 2, wo = wid & 3, gtid = tid & 127;
    const int q = lane >> 3, rr = lane & 7;

    // ldmatrix per-lane byte offsets
    // A (W^T, stride 36 words): matrices (m0-7,k0),(m8-15,k0),(m0-7,k1),(m8-15,k1)
    const uint32_t aoffW = (uint32_t)(((wo * 16 + (q & 1) * 8 + rr) * 36 + (q >> 1) * 4) * 4);
    // B (x, stride 36): matrices (n0-7,k0),(n0-7,k1),(n8-15,k0),(n8-15,k1)
    const uint32_t boffX = (uint32_t)((((q >> 1) * 8 + rr) * 36 + (q & 1) * 4) * 4);
    // B (adj, stride 52): same pattern
    const uint32_t boffA = (uint32_t)((((q >> 1) * 8 + rr) * 52 + (q & 1) * 4) * 4);

    // ---- prologue ----
    for (int i = tid; i < 2496; i += NT) sm[ADJ_OFF + i] = 0;   // adj zero (incl pads)
    for (int i = tid; i < 4 * 5 * 36; i += NT) {                // x pad rows 43..47
        int gg = i / 180, r = i % 180;
        sm[X_OFF + gg * XW + (NV + r / 36) * 36 + (r % 36)] = 0;
    }
    for (int idx = tid; idx < 2 * 64 * 64; idx += NT) {         // W^T hi/lo split
        int s = idx >> 12, i = (idx >> 6) & 63, o = idx & 63;
        float w = gw[idx];
        __half hh = __float2half_rn(w);
        __half hl = __float2half_rn(w - __half2float(hh));
        int ha = (s * 64 + o) * 72 + i;
        shw[WTH_OFF * 2 + ha] = *(uint16_t*)&hh;
        shw[WTL_OFF * 2 + ha] = *(uint16_t*)&hl;
    }
    __syncthreads();
    for (int idx = tid; idx < 2 * NV * NV; idx += NT) {         // adj fp16 fill
        int s = idx / (NV * NV), r = idx % (NV * NV), u = r / NV, v = r % NV;
        __half h = __float2half_rn(gadj[idx]);
        shw[ADJ_OFF * 2 + u * 104 + s * 48 + v] = *(uint16_t*)&h;
    }
    const float b0 = gb[wo * 16 + g];
    const float b1 = gb[wo * 16 + g + 8];
    __syncthreads();

    const uint32_t wth_b = sb + WTH_OFF * 4;
    const uint32_t wtl_b = sb + WTL_OFF * 4;
    const uint32_t adj_b = sb + ADJ_OFF * 4;
    const uint32_t x_b   = sb + (X_OFF + grp * XW) * 4;
    uint32_t* xg = sm + X_OFF + grp * XW;
    const int bar = grp + 1;

    for (int it = 0; it < IT; ++it) {
        const size_t b = ((size_t)blockIdx.x * 4 + grp) * IT + it;

        // ---- group-cooperative x load, fp16 convert ----
        barg(bar);
        {
            const float4* src = (const float4*)(gx + b * (NV * 64));
            for (int j = gtid; j < NV * 16; j += 128) {
                float4 f = src[j];
                uint32_t* dst = xg + (j >> 4) * 36 + (j & 15) * 2;
                dst[0] = f16x2(f.y, f.x);
                dst[1] = f16x2(f.w, f.z);
            }
        }
        barg(bar);

        // ---- Phase B: pre^T[o(16)][v(48)] per support, acc in regs ----
        float accB[2][6][4];
        #pragma unroll
        for (int s = 0; s < 2; ++s)
            #pragma unroll
            for (int nt = 0; nt < 6; ++nt)
                #pragma unroll
                for (int j = 0; j < 4; ++j) accB[s][nt][j] = 0.f;

        #pragma unroll
        for (int kt = 0; kt < 4; ++kt) {
            uint32_t bx[3][4], wh_[2][4], wl_[2][4];
            #pragma unroll
            for (int nb = 0; nb < 3; ++nb)
                ldsm4(bx[nb], x_b + (uint32_t)(nb * 16 * 36 * 4) + kt * 32 + boffX);
            #pragma unroll
            for (int s = 0; s < 2; ++s) {
                ldsm4(wh_[s], wth_b + (uint32_t)(s * 64 * 36 * 4) + kt * 32 + aoffW);
                ldsm4(wl_[s], wtl_b + (uint32_t)(s * 64 * 36 * 4) + kt * 32 + aoffW);
            }
            #pragma unroll
            for (int s = 0; s < 2; ++s)
                #pragma unroll
                for (int nt = 0; nt < 6; ++nt)
                    mma16(accB[s][nt], wh_[s], &bx[nt >> 1][(nt & 1) * 2]);
            #pragma unroll
            for (int s = 0; s < 2; ++s)
                #pragma unroll
                for (int nt = 0; nt < 6; ++nt)
                    mma16(accB[s][nt], wl_[s], &bx[nt >> 1][(nt & 1) * 2]);
        }

        // ---- convert accB -> phase-C A fragments (hi + lo), registers only ----
        uint32_t pah[6][4], pal[6][4];
        #pragma unroll
        for (int s = 0; s < 2; ++s)
            #pragma unroll
            for (int vb = 0; vb < 3; ++vb) {
                const int k6 = s * 3 + vb;
                const float* c = accB[s][2 * vb];
                const float* d = accB[s][2 * vb + 1];
                pah[k6][0] = f16x2(c[1], c[0]);
                pah[k6][1] = f16x2(c[3], c[2]);
                pah[k6][2] = f16x2(d[1], d[0]);
                pah[k6][3] = f16x2(d[3], d[2]);
                float2 r;
                r = unpack_h2(pah[k6][0]); pal[k6][0] = f16x2(c[1] - r.y, c[0] - r.x);
                r = unpack_h2(pah[k6][1]); pal[k6][1] = f16x2(c[3] - r.y, c[2] - r.x);
                r = unpack_h2(pah[k6][2]); pal[k6][2] = f16x2(d[1] - r.y, d[0] - r.x);
                r = unpack_h2(pah[k6][3]); pal[k6][3] = f16x2(d[3] - r.y, d[2] - r.x);
            }

        // ---- Phase C: out^T[o(16)][u(48)] = pre^T @ adj^T ----
        float oc[6][4];
        #pragma unroll
        for (int nt = 0; nt < 6; ++nt) {
            oc[nt][0] = b0; oc[nt][1] = b0; oc[nt][2] = b1; oc[nt][3] = b1;
        }
        #pragma unroll
        for (int kt = 0; kt < 6; ++kt) {
            uint32_t ba[3][4];
            #pragma unroll
            for (int ub = 0; ub < 3; ++ub)
                ldsm4(ba[ub], adj_b + (uint32_t)(ub * 16 * 52 * 4) + kt * 32 + boffA);
            #pragma unroll
            for (int nt = 0; nt < 6; ++nt)
                mma16(oc[nt], pah[kt], &ba[nt >> 1][(nt & 1) * 2]);
            #pragma unroll
            for (int nt = 0; nt < 6; ++nt)
                mma16(oc[nt], pal[kt], &ba[nt >> 1][(nt & 1) * 2]);
        }

        // ---- epilogue: relu + store (out^T layout -> out[b][u][o]) ----
        {
            float* op = gout + b * (NV * 64);
            const int o0 = wo * 16 + g, o1 = o0 + 8;
            #pragma unroll
            for (int nt = 0; nt < 5; ++nt) {
                const int u0 = nt * 8 + 2 * t;
                op[u0 * 64 + o0]       = fmaxf(oc[nt][0], 0.f);
                op[(u0 + 1) * 64 + o0] = fmaxf(oc[nt][1], 0.f);
                op[u0 * 64 + o1]       = fmaxf(oc[nt][2], 0.f);
                op[(u0 + 1) * 64 + o1] = fmaxf(oc[nt][3], 0.f);
            }
            const int u0 = 40 + 2 * t;
            if (u0 < NV) {
                op[u0 * 64 + o0] = fmaxf(oc[5][0], 0.f);
                op[u0 * 64 + o1] = fmaxf(oc[5][2], 0.f);
            }
            if (u0 + 1 < NV) {
                op[(u0 + 1) * 64 + o0] = fmaxf(oc[5][1], 0.f);
                op[(u0 + 1) * 64 + o1] = fmaxf(oc[5][3], 0.f);
            }
        }
    }
}

extern "C" void kernel_launch(void* const* d_in, const int* in_sizes, int n_in,
                              void* d_out, int out_size) {
    const float* x   = (const float*)d_in[0];
    const float* adj = (const float*)d_in[1];
    const float* W   = (const float*)d_in[2];
    const float* b   = (const float*)d_in[3];
    float* out = (float*)d_out;

    cudaFuncSetAttribute(lgconv_fp16, cudaFuncAttributeMaxDynamicSharedMemorySize, SMEM_BYTES);
    lgconv_fp16<<<GRID, NT, SMEM_BYTES>>>(x, adj, W, b, out);
}

// round 8
// speedup vs baseline: 7.5009x; 1.4917x over previous
#include <cuda_runtime.h>
#include <cuda_fp16.h>
#include <cstdint>

// LocalGConv fp16 MMA, pre register-resident, double-buffered x:
//   phase B (transposed): pre^T[o=16][v=48] = W_s^T @ x^T, 2-term W split
//   phase C (normal):     out[u=48][o=16] = adjcat @ pre, single-term
// B=32768, V=43 (pad 48), DIN=DOUT=64, S=2.
// 512 threads = 16 warps = 4 groups; group owns one batch/iter; warp owns 16 o.

#define NT   512
#define GRID 2048
#define IT   4
#define NV   43

// SMEM word offsets
#define WTH_OFF 0        // W^T hi: [s*64+o rows][36 words]
#define WTL_OFF 4608     // W^T lo
#define ADJ_OFF 9216     // adj fp16: [48 u rows][52 words], k = s*48+v
#define X_OFF   11712    // [2 bufs][4 groups][48 rows][36 words]
#define XW      1728
#define SMEM_WORDS (X_OFF + 2 * 4 * XW)
#define SMEM_BYTES (SMEM_WORDS * 4)   // 102,144 B

static __device__ __forceinline__ void mma16(float* d, const uint32_t* a, const uint32_t* b) {
    asm volatile(
        "mma.sync.aligned.m16n8k16.row.col.f32.f16.f16.f32 "
        "{%0,%1,%2,%3},{%4,%5,%6,%7},{%8,%9},{%0,%1,%2,%3};"
        : "+f"(d[0]), "+f"(d[1]), "+f"(d[2]), "+f"(d[3])
        : "r"(a[0]), "r"(a[1]), "r"(a[2]), "r"(a[3]), "r"(b[0]), "r"(b[1]));
}
static __device__ __forceinline__ void ldsm4(uint32_t* d, uint32_t addr) {
    asm volatile("ldmatrix.sync.aligned.m8n8.x4.shared.b16 {%0,%1,%2,%3}, [%4];"
        : "=r"(d[0]), "=r"(d[1]), "=r"(d[2]), "=r"(d[3]) : "r"(addr));
}
static __device__ __forceinline__ uint32_t su32(const void* p) {
    uint32_t a;
    asm("{ .reg .u64 t; cvta.to.shared.u64 t, %1; cvt.u32.u64 %0, t; }" : "=r"(a) : "l"(p));
    return a;
}
static __device__ __forceinline__ uint32_t f16x2(float hi, float lo) {
    uint32_t d;
    asm("cvt.rn.f16x2.f32 %0, %1, %2;" : "=r"(d) : "f"(hi), "f"(lo));
    return d;
}
static __device__ __forceinline__ void barg(int bid) {
    asm volatile("bar.sync %0, 128;" :: "r"(bid) : "memory");
}

__global__ __launch_bounds__(NT, 1)
void lgconv_fp16(const float* __restrict__ gx, const float* __restrict__ gadj,
                 const float* __restrict__ gw, const float* __restrict__ gb,
                 float* __restrict__ gout)
{
    extern __shared__ uint32_t sm[];
    uint16_t* shw = (uint16_t*)sm;
    const uint32_t sb = su32(sm);
    const int tid = threadIdx.x, wid = tid >> 5, lane = tid & 31;
    const int g = lane >> 2, t = lane & 3;
    const int grp = wid >> 2, wo = wid & 3, gtid = tid & 127;
    const int q = lane >> 3, rr = lane & 7;

    // ldmatrix per-lane byte offsets
    const uint32_t aoffW = (uint32_t)(((wo * 16 + (q & 1) * 8 + rr) * 36 + (q >> 1) * 4) * 4);
    const uint32_t boffX = (uint32_t)((((q >> 1) * 8 + rr) * 36 + (q & 1) * 4) * 4);
    const uint32_t aoffA = (uint32_t)((((q & 1) * 8 + rr) * 52 + (q >> 1) * 4) * 4);

    // ---- prologue: W^T hi/lo, adj fp16 (zero-padded) ----
    for (int i = tid; i < 2496; i += NT) sm[ADJ_OFF + i] = 0;
    for (int i = tid; i < 2 * 4 * 5 * 36; i += NT) {   // x pad rows 43..47, both bufs
        int bg = i / 180, r = i % 180;
        sm[X_OFF + bg * XW + (NV + r / 36) * 36 + (r % 36)] = 0;
    }
    for (int idx = tid; idx < 2 * 64 * 64; idx += NT) {
        int s = idx >> 12, i = (idx >> 6) & 63, o = idx & 63;
        float w = gw[idx];
        __half hh = __float2half_rn(w);
        __half hl = __float2half_rn(w - __half2float(hh));
        int ha = (s * 64 + o) * 72 + i;
        shw[WTH_OFF * 2 + ha] = *(uint16_t*)&hh;
        shw[WTL_OFF * 2 + ha] = *(uint16_t*)&hl;
    }
    __syncthreads();
    for (int idx = tid; idx < 2 * NV * NV; idx += NT) {
        int s = idx / (NV * NV), r = idx % (NV * NV), u = r / NV, v = r % NV;
        __half h = __float2half_rn(gadj[idx]);
        shw[ADJ_OFF * 2 + u * 104 + s * 48 + v] = *(uint16_t*)&h;
    }
    float2 bb[2];
    #pragma unroll
    for (int oh = 0; oh < 2; ++oh)
        bb[oh] = *(const float2*)(gb + wo * 16 + oh * 8 + 2 * t);

    const uint32_t wth_b = sb + WTH_OFF * 4;
    const uint32_t wtl_b = sb + WTL_OFF * 4;
    const uint32_t adj_b = sb + ADJ_OFF * 4;
    const size_t bbase = (size_t)(blockIdx.x * 4 + grp) * IT;

    // ---- initial x load into buffer 0 ----
    {
        uint32_t* xg = sm + X_OFF + grp * XW;
        const float4* src = (const float4*)(gx + bbase * (NV * 64));
        for (int j = gtid; j < NV * 16; j += 128) {
            float4 f = src[j];
            uint32_t* dst = xg + (j >> 4) * 36 + (j & 15) * 2;
            dst[0] = f16x2(f.y, f.x);
            dst[1] = f16x2(f.w, f.z);
        }
    }
    __syncthreads();

    const int bar = grp + 1;

    for (int it = 0; it < IT; ++it) {
        const size_t b = bbase + it;
        const int cur = it & 1, nxt = cur ^ 1;
        const uint32_t x_b = sb + (X_OFF + (cur * 4 + grp) * XW) * 4;
        const bool pf = (it + 1 < IT);

        // ---- Phase B: pre^T[o][v] per support (2-term W split) ----
        float accB[2][6][4];
        #pragma unroll
        for (int s = 0; s < 2; ++s)
            #pragma unroll
            for (int nt = 0; nt < 6; ++nt)
                #pragma unroll
                for (int j = 0; j < 4; ++j) accB[s][nt][j] = 0.f;

        #pragma unroll
        for (int kt = 0; kt < 4; ++kt) {
            uint32_t bx[3][4], wh_[2][4], wl_[2][4];
            #pragma unroll
            for (int nb = 0; nb < 3; ++nb)
                ldsm4(bx[nb], x_b + (uint32_t)(nb * 16 * 36 * 4) + kt * 32 + boffX);
            #pragma unroll
            for (int s = 0; s < 2; ++s) {
                ldsm4(wh_[s], wth_b + (uint32_t)(s * 64 * 36 * 4) + kt * 32 + aoffW);
                ldsm4(wl_[s], wtl_b + (uint32_t)(s * 64 * 36 * 4) + kt * 32 + aoffW);
            }
            #pragma unroll
            for (int s = 0; s < 2; ++s)
                #pragma unroll
                for (int nt = 0; nt < 6; ++nt)
                    mma16(accB[s][nt], wh_[s], &bx[nt >> 1][(nt & 1) * 2]);
            #pragma unroll
            for (int s = 0; s < 2; ++s)
                #pragma unroll
                for (int nt = 0; nt < 6; ++nt)
                    mma16(accB[s][nt], wl_[s], &bx[nt >> 1][(nt & 1) * 2]);
        }

        // ---- pack accB -> phase-C B-fragments (registers only, single-term) ----
        uint32_t pb[2][3][2][2];   // [s][vb][oh][b0,b1]
        #pragma unroll
        for (int s = 0; s < 2; ++s)
            #pragma unroll
            for (int vb = 0; vb < 3; ++vb) {
                const float* c = accB[s][2 * vb];
                const float* d = accB[s][2 * vb + 1];
                pb[s][vb][0][0] = f16x2(c[1], c[0]);
                pb[s][vb][1][0] = f16x2(c[3], c[2]);
                pb[s][vb][0][1] = f16x2(d[1], d[0]);
                pb[s][vb][1][1] = f16x2(d[3], d[2]);
            }

        // ---- prefetch next x into registers (latency covered by phase C) ----
        float4 xf[6];
        const float4* srcn = (const float4*)(gx + (b + 1) * (NV * 64));
        if (pf) {
            #pragma unroll
            for (int j = 0; j < 6; ++j) {
                int idx = gtid + j * 128;
                if (idx < NV * 16) xf[j] = srcn[idx];
            }
        }

        // ---- Phase C: out[u][own o] = bias + adjcat @ pre ----
        float oc[3][2][4];
        #pragma unroll
        for (int mt = 0; mt < 3; ++mt)
            #pragma unroll
            for (int oh = 0; oh < 2; ++oh) {
                oc[mt][oh][0] = bb[oh].x; oc[mt][oh][1] = bb[oh].y;
                oc[mt][oh][2] = bb[oh].x; oc[mt][oh][3] = bb[oh].y;
            }
        #pragma unroll
        for (int s = 0; s < 2; ++s)
            #pragma unroll
            for (int vb = 0; vb < 3; ++vb) {
                const uint32_t kb = (uint32_t)(s * 3 + vb) * 32;
                uint32_t ba[3][4];
                #pragma unroll
                for (int mt = 0; mt < 3; ++mt)
                    ldsm4(ba[mt], adj_b + (uint32_t)(mt * 16 * 52 * 4) + kb + aoffA);
                #pragma unroll
                for (int mt = 0; mt < 3; ++mt)
                    #pragma unroll
                    for (int oh = 0; oh < 2; ++oh)
                        mma16(oc[mt][oh], ba[mt], pb[s][vb][oh]);
            }

        // ---- epilogue: relu + coalesced float2 stores ----
        {
            float* op = gout + b * (NV * 64) + wo * 16 + 2 * t;
            #pragma unroll
            for (int mt = 0; mt < 3; ++mt)
                #pragma unroll
                for (int oh = 0; oh < 2; ++oh) {
                    const int u0 = mt * 16 + g, u1 = u0 + 8;
                    *(float2*)(op + u0 * 64 + oh * 8) =
                        make_float2(fmaxf(oc[mt][oh][0], 0.f), fmaxf(oc[mt][oh][1], 0.f));
                    if (u1 < NV)
                        *(float2*)(op + u1 * 64 + oh * 8) =
                            make_float2(fmaxf(oc[mt][oh][2], 0.f), fmaxf(oc[mt][oh][3], 0.f));
                }
        }

        // ---- store prefetched x to alternate buffer + group barrier ----
        if (pf) {
            uint32_t* xg = sm + X_OFF + (nxt * 4 + grp) * XW;
            #pragma unroll
            for (int j = 0; j < 6; ++j) {
                int idx = gtid + j * 128;
                if (idx < NV * 16) {
                    uint32_t* dst = xg + (idx >> 4) * 36 + (idx & 15) * 2;
                    dst[0] = f16x2(xf[j].y, xf[j].x);
                    dst[1] = f16x2(xf[j].w, xf[j].z);
                }
            }
            barg(bar);
        }
    }
}

extern "C" void kernel_launch(void* const* d_in, const int* in_sizes, int n_in,
                              void* d_out, int out_size) {
    const float* x   = (const float*)d_in[0];
    const float* adj = (const float*)d_in[1];
    const float* W   = (const float*)d_in[2];
    const float* b   = (const float*)d_in[3];
    float* out = (float*)d_out;

    cudaFuncSetAttribute(lgconv_fp16, cudaFuncAttributeMaxDynamicSharedMemorySize, SMEM_BYTES);
    lgconv_fp16<<<GRID, NT, SMEM_BYTES>>>(x, adj, W, b, out);
}